// round 11
// baseline (speedup 1.0000x reference)
#include <cuda_runtime.h>

// rho' = L rho L^T,  L = A (x) B (x) C  (flat = r*64 + c*4 + j; r,c in [0,16),
// j in [0,4)).  A,B identity outside 0..3 -> independent row classes:
//   D  : {r<4,c<4}   64 rows  -> blocks 0..15  (smem, 64x64)
//   chunk-0 16-row classes    -> blocks 16..75 (reg path + smem col-A stage)
//   chunk!=0 16-row classes   -> blocks 76..435: HALF-COLUMN register path:
//        thread owns 8 rows of one column; cross-sub row mix via shfl.xor 16;
//        column-side C/B via warp shuffles; 0 syncs, 0 smem.
// Grid 436 blocks (occ ~37%), per-thread light work: 8 LDG + ~64 SHFL.

__device__ __forceinline__ void mix4s(float* p, const int st, const float* M)
{
    float v0 = p[0], v1 = p[st], v2 = p[2*st], v3 = p[3*st];
    p[0]    = M[0] *v0 + M[1] *v1 + M[2] *v2 + M[3] *v3;
    p[st]   = M[4] *v0 + M[5] *v1 + M[6] *v2 + M[7] *v3;
    p[2*st] = M[8] *v0 + M[9] *v1 + M[10]*v2 + M[11]*v3;
    p[3*st] = M[12]*v0 + M[13]*v1 + M[14]*v2 + M[15]*v3;
}

__device__ __forceinline__ void mix4r(float* v, const int st, const float* M)
{
    float v0 = v[0], v1 = v[st], v2 = v[2*st], v3 = v[3*st];
    v[0]    = M[0] *v0 + M[1] *v1 + M[2] *v2 + M[3] *v3;
    v[st]   = M[4] *v0 + M[5] *v1 + M[6] *v2 + M[7] *v3;
    v[2*st] = M[8] *v0 + M[9] *v1 + M[10]*v2 + M[11]*v3;
    v[3*st] = M[12]*v0 + M[13]*v1 + M[14]*v2 + M[15]*v3;
}

__device__ __forceinline__ float4 mixf4(float4 v, const float* M)
{
    float4 r;
    r.x = M[0] *v.x + M[1] *v.y + M[2] *v.z + M[3] *v.w;
    r.y = M[4] *v.x + M[5] *v.y + M[6] *v.z + M[7] *v.w;
    r.z = M[8] *v.x + M[9] *v.y + M[10]*v.z + M[11]*v.w;
    r.w = M[12]*v.x + M[13]*v.y + M[14]*v.z + M[15]*v.w;
    return r;
}

__device__ __forceinline__ void mixquad(float4* y, const float* M)
{
    float4 v0 = y[0], v1 = y[1], v2 = y[2], v3 = y[3];
#define MQ(c) \
    y[0].c = M[0] *v0.c + M[1] *v1.c + M[2] *v2.c + M[3] *v3.c; \
    y[1].c = M[4] *v0.c + M[5] *v1.c + M[6] *v2.c + M[7] *v3.c; \
    y[2].c = M[8] *v0.c + M[9] *v1.c + M[10]*v2.c + M[11]*v3.c; \
    y[3].c = M[12]*v0.c + M[13]*v1.c + M[14]*v2.c + M[15]*v3.c;
    MQ(x) MQ(y) MQ(z) MQ(w)
#undef MQ
}

// Per-warp matrix build: lane L computes the Givens product for (L % 3);
// lanes 0/1/2 hold A/B/C, broadcast via shuffles. No barriers.
__device__ __forceinline__ void build_mats(const float* __restrict__ thetas,
                                           int lane,
                                           float* A4, float* B4, float* C4)
{
    float M[16] = {1,0,0,0, 0,1,0,0, 0,0,1,0, 0,0,0,1};
    const int pi[6] = {0,0,0,1,1,2};
    const int pj[6] = {1,2,3,2,3,3};
    const int base = (lane % 3) * 6;
#pragma unroll
    for (int g = 0; g < 6; ++g) {
        float th = thetas[base + g];
        float sn, cs;
        __sincosf(th, &sn, &cs);
        int i = pi[g], j = pj[g];
#pragma unroll
        for (int k = 0; k < 4; ++k) {
            float ai = M[i*4 + k], aj = M[j*4 + k];
            M[i*4 + k] =  cs * ai + sn * aj;   // M <- G * M
            M[j*4 + k] = -sn * ai + cs * aj;
        }
    }
#pragma unroll
    for (int k = 0; k < 16; ++k) {
        A4[k] = __shfl_sync(0xffffffffu, M[k], 0);
        B4[k] = __shfl_sync(0xffffffffu, M[k], 1);
        C4[k] = __shfl_sync(0xffffffffu, M[k], 2);
    }
}

// Column-side C and B mixes on a full register column v[16]; t = col [0,256).
__device__ __forceinline__ void colmix_CB(float* v, int t,
                                          const float* B4, const float* C4)
{
    const unsigned F = 0xffffffffu;
    const int lane = t & 31;
    const int j  = lane & 3;
    const int bj = lane & ~3;
    float c0 = C4[j*4+0], c1 = C4[j*4+1], c2 = C4[j*4+2], c3 = C4[j*4+3];
#pragma unroll
    for (int l = 0; l < 16; ++l) {
        float x  = v[l];
        float s0 = __shfl_sync(F, x, bj + 0);
        float s1 = __shfl_sync(F, x, bj + 1);
        float s2 = __shfl_sync(F, x, bj + 2);
        float s3 = __shfl_sync(F, x, bj + 3);
        v[l] = c0*s0 + c1*s1 + c2*s2 + c3*s3;
    }
    if ((t & 32) == 0) {                       // low warp of each 64-col group
        const int  cg  = (t >> 2) & 15;
        const bool doB = (cg < 4);
        const int  ci  = doB ? cg : 0;
        float b0 = B4[ci*4+0], b1 = B4[ci*4+1], b2 = B4[ci*4+2], b3 = B4[ci*4+3];
#pragma unroll
        for (int l = 0; l < 16; ++l) {
            float x  = v[l];
            float s0 = __shfl_sync(F, x, j + 0);
            float s1 = __shfl_sync(F, x, j + 4);
            float s2 = __shfl_sync(F, x, j + 8);
            float s3 = __shfl_sync(F, x, j + 12);
            float nv = b0*s0 + b1*s1 + b2*s2 + b3*s3;
            if (doB) v[l] = nv;
        }
    }
}

// class decode for 16-row blocks: cls in [0,60)
__device__ __forceinline__ int class_row(int cls, int l)
{
    if (cls < 12)  return (4 + cls) * 64 + l;                           // Bc
    if (cls < 24)  return (l >> 2) * 64 + (4 + cls - 12) * 4 + (l & 3); // Cc
    int g = cls - 24;                                                   // Am
    return (4 + g / 3) * 64 + (4 + (g % 3) * 4) * 4 + l;
}

__global__ __launch_bounds__(256)
void rbs_fused(const float* __restrict__ in, float* __restrict__ out,
               const float* __restrict__ thetas)
{
    __shared__ float s[5120];   // D: 64x80 ; chunk-0 generic: 16x320

    const int t = threadIdx.x;
    const int b = blockIdx.x;
    const int lane = t & 31;

    const float4* in4  = reinterpret_cast<const float4*>(in);
    float4*       out4 = reinterpret_cast<float4*>(out);

    if (b >= 76) {
        // ===== LIGHT: 16-row classes, chunk!=0, half-column per thread =====
        const int id = b - 76;
        const int cls = id / 6, rem = id - cls * 6;
        const int chunk = 1 + (rem >> 1), half = rem & 1;
        const int typ = (cls < 12) ? 0 : (cls < 24) ? 1 : 2;
        const int sub = lane >> 4;                 // 0: rows 0-7, 1: rows 8-15
        const int colIdx = (t >> 5) * 16 + (lane & 15);
        const int gcol = chunk * 256 + half * 128 + colIdx;

        float v[8];
#pragma unroll
        for (int k = 0; k < 8; ++k)
            v[k] = in[(size_t)class_row(cls, sub * 8 + k) * 1024 + gcol];

        float A4[16], B4[16], C4[16];
        build_mats(thetas, lane, A4, B4, C4);
        const unsigned F = 0xffffffffu;

        // row C on j within the two quads this thread owns
        mix4r(&v[0], 1, C4);
        mix4r(&v[4], 1, C4);

        // row B (Bc) / row A (Cc) across c/r: 4-vector split across sub pair
        if (typ != 2) {
            const float* M2 = (typ == 0) ? B4 : A4;
#pragma unroll
            for (int j = 0; j < 4; ++j) {
                float a0 = v[j], a1 = v[4 + j];
                float p0 = __shfl_xor_sync(F, a0, 16);
                float p1 = __shfl_xor_sync(F, a1, 16);
                float f0 = sub ? p0 : a0;
                float f1 = sub ? p1 : a1;
                float f2 = sub ? a0 : p0;
                float f3 = sub ? a1 : p1;
                int c0 = 2 * sub, c1 = c0 + 1;
                v[j]     = M2[c0*4+0]*f0 + M2[c0*4+1]*f1 + M2[c0*4+2]*f2 + M2[c0*4+3]*f3;
                v[4 + j] = M2[c1*4+0]*f0 + M2[c1*4+1]*f1 + M2[c1*4+2]*f2 + M2[c1*4+3]*f3;
            }
        }

        // col C: j-quads of columns = lanes (lane&~3) .. +3 (stays in half)
        {
            const int j = lane & 3, bj = lane & ~3;
            float c0 = C4[j*4+0], c1 = C4[j*4+1], c2 = C4[j*4+2], c3 = C4[j*4+3];
#pragma unroll
            for (int l = 0; l < 8; ++l) {
                float x  = v[l];
                float s0 = __shfl_sync(F, x, bj + 0);
                float s1 = __shfl_sync(F, x, bj + 1);
                float s2 = __shfl_sync(F, x, bj + 2);
                float s3 = __shfl_sync(F, x, bj + 3);
                v[l] = c0*s0 + c1*s1 + c2*s2 + c3*s3;
            }
        }
        // col B: warps with gcol%64 < 16 are exactly w%4==0 (base%64==0);
        // there all lanes have c' = (lane&15)>>2 in 0..3.
        if (((t >> 5) & 3) == 0) {
            const int j  = lane & 3;
            const int cg = (lane & 15) >> 2;
            const int hb = lane & 16;
            float b0 = B4[cg*4+0], b1 = B4[cg*4+1], b2 = B4[cg*4+2], b3 = B4[cg*4+3];
#pragma unroll
            for (int l = 0; l < 8; ++l) {
                float x  = v[l];
                float s0 = __shfl_sync(F, x, hb | (j + 0));
                float s1 = __shfl_sync(F, x, hb | (j + 4));
                float s2 = __shfl_sync(F, x, hb | (j + 8));
                float s3 = __shfl_sync(F, x, hb | (j + 12));
                v[l] = b0*s0 + b1*s1 + b2*s2 + b3*s3;
            }
        }

#pragma unroll
        for (int k = 0; k < 8; ++k)
            out[(size_t)class_row(cls, sub * 8 + k) * 1024 + gcol] = v[k];

    } else if (b >= 16) {
        // ===== CHUNK-0 16-row classes: full column + smem col-A stage ======
        const int cls = b - 16;
        const int typ = (cls < 12) ? 0 : (cls < 24) ? 1 : 2;
        const int gcol = t;                        // chunk 0

        float v[16];
#pragma unroll
        for (int l = 0; l < 16; ++l)
            v[l] = in[(size_t)class_row(cls, l) * 1024 + gcol];

        float A4[16], B4[16], C4[16];
        build_mats(thetas, lane, A4, B4, C4);

#pragma unroll
        for (int q = 0; q < 4; ++q) mix4r(&v[q*4], 1, C4);        // row C
        if (typ == 0) {
#pragma unroll
            for (int j2 = 0; j2 < 4; ++j2) mix4r(&v[j2], 4, B4);  // row B
        } else if (typ == 1) {
#pragma unroll
            for (int j2 = 0; j2 < 4; ++j2) mix4r(&v[j2], 4, A4);  // row A
        }

        // col A (rc'<4 = cols 0..255) via padded smem
        {
            const int pc = t + 4 * (t >> 4);
#pragma unroll
            for (int l = 0; l < 16; ++l) s[l*320 + pc] = v[l];
            __syncthreads();
#pragma unroll
            for (int h = 0; h < 4; ++h) {
                int g2 = t + 256*h;
                int l2 = g2 >> 6, q = g2 & 63;
                mix4s(&s[l2*320 + q + 4*(q >> 4)], 80, A4);
            }
            __syncthreads();
#pragma unroll
            for (int l = 0; l < 16; ++l) v[l] = s[l*320 + pc];
        }

        colmix_CB(v, t, B4, C4);
#pragma unroll
        for (int l = 0; l < 16; ++l)
            out[(size_t)class_row(cls, l) * 1024 + gcol] = v[l];

    } else {
        // ========== TYPE D: 64 rows {r<4,c<4} x 64 cols (blocks 0..15) =====
        const int ccq = b & 3, chunk = b >> 2;
        const int l = t >> 2, rcl = t & 3;
        const int grow = (l >> 4)*64 + (l & 15);
        const int gb = (chunk*4 + rcl)*16 + ccq*4;

        {
            float4 x[4];
#pragma unroll
            for (int w = 0; w < 4; ++w) x[w] = in4[grow*256 + gb + w];
#pragma unroll
            for (int w = 0; w < 4; ++w)
                *reinterpret_cast<float4*>(&s[l*80 + rcl*20 + w*4]) = x[w];
        }
        float A4[16], B4[16], C4[16];
        build_mats(thetas, lane, A4, B4, C4);
        __syncthreads();

        {
            const int rr = t >> 6, q = t & 63;
            const int pc = q + 4*(q >> 4);
            float v[16];
#pragma unroll
            for (int k = 0; k < 16; ++k) v[k] = s[(rr*16 + k)*80 + pc];
#pragma unroll
            for (int cc = 0; cc < 4; ++cc) mix4r(&v[cc*4], 1, C4);
#pragma unroll
            for (int j = 0; j < 4; ++j)    mix4r(&v[j], 4, B4);
#pragma unroll
            for (int k = 0; k < 16; ++k) s[(rr*16 + k)*80 + pc] = v[k];
        }
        __syncthreads();

#pragma unroll
        for (int h = 0; h < 4; ++h) {
            int g2 = t + 256*h;
            int ccj = g2 >> 6, q = g2 & 63;
            mix4s(&s[ccj*80 + q + 4*(q >> 4)], 16*80, A4);
        }
        __syncthreads();

        if (chunk == 0) {
#pragma unroll
            for (int h = 0; h < 4; ++h) {
                int g2 = t + 256*h;
                int l2 = g2 >> 4, wj = g2 & 15;
                mix4s(&s[l2*80 + wj], 20, A4);
            }
            __syncthreads();
        }

        {
            float4 y[4];
#pragma unroll
            for (int w = 0; w < 4; ++w)
                y[w] = *reinterpret_cast<float4*>(&s[l*80 + rcl*20 + w*4]);
            if (ccq == 0) mixquad(y, B4);
#pragma unroll
            for (int w = 0; w < 4; ++w)
                out4[grow*256 + gb + w] = mixf4(y[w], C4);
        }
    }
}

extern "C" void kernel_launch(void* const* d_in, const int* in_sizes, int n_in,
                              void* d_out, int out_size)
{
    const float* state  = nullptr;
    const float* thetas = nullptr;
    for (int i = 0; i < n_in; ++i) {
        if (in_sizes[i] == 18 && !thetas)
            thetas = (const float*)d_in[i];
        else if (in_sizes[i] == 1024 * 1024 && !state)
            state = (const float*)d_in[i];
    }
    rbs_fused<<<436, 256>>>(state, (float*)d_out, thetas);
}

// round 12
// speedup vs baseline: 1.0791x; 1.0791x over previous
#include <cuda_runtime.h>

// rho' = L rho L^T,  L = A (x) B (x) C  (flat index = r*64 + c*4 + j,
// r,c in [0,16), j in [0,4)).  A,B are identity outside indices 0..3, so the
// index space splits into independent coupling classes:
//   D : {r<4, c<4}                -> one class of 64 indices
//   Cc: {r<4, c fixed >=4}        -> 12 classes of 16
//   Bc: {r fixed >=4, c<4}        -> 12 classes of 16
//   Am: {r>=4, c>=4}              -> 144 classes of 4 (merged 4-at-a-time)
// out[I,J] = (L|I) rho[I,J] (L|J)^T per class pair, so ONE kernel: each block
// owns a row-class x column range of whole column classes, applies row mixing
// (in registers) and column mixing (in padded smem), reads/writes each element
// exactly once, fully coalesced. No scratch, no second pass, no transpose.
//
// Best-measured variant (9.28 us wall, rel_err 1.39e-7). Converged: occupancy,
// sync-count, and shuffle-based restructures all measured neutral-to-worse;
// wall is pinned by replay overhead + an irreducible latency chain.

#define RS16 272   // 16-row tiles: 256 cols + 4 pad per 64-col block
#define RSD   80   // 64-row tiles:  64 cols + 4 pad per 16-col block

__device__ __forceinline__ void mix4s(float* p, const int st, const float* M)
{
    float v0 = p[0], v1 = p[st], v2 = p[2*st], v3 = p[3*st];
    p[0]    = M[0] *v0 + M[1] *v1 + M[2] *v2 + M[3] *v3;
    p[st]   = M[4] *v0 + M[5] *v1 + M[6] *v2 + M[7] *v3;
    p[2*st] = M[8] *v0 + M[9] *v1 + M[10]*v2 + M[11]*v3;
    p[3*st] = M[12]*v0 + M[13]*v1 + M[14]*v2 + M[15]*v3;
}

__device__ __forceinline__ void mix4r(float* v, const int st, const float* M)
{
    float v0 = v[0], v1 = v[st], v2 = v[2*st], v3 = v[3*st];
    v[0]    = M[0] *v0 + M[1] *v1 + M[2] *v2 + M[3] *v3;
    v[st]   = M[4] *v0 + M[5] *v1 + M[6] *v2 + M[7] *v3;
    v[2*st] = M[8] *v0 + M[9] *v1 + M[10]*v2 + M[11]*v3;
    v[3*st] = M[12]*v0 + M[13]*v1 + M[14]*v2 + M[15]*v3;
}

__global__ __launch_bounds__(256)
void rbs_fused(const float* __restrict__ in, float* __restrict__ out,
               const float* __restrict__ thetas)
{
    __shared__ float s[64 * RSD];   // 20480 B; 16*RS16 = 4352 floats also fits
    __shared__ float sM[3][16];     // 0:A (row gates), 1:B (col), 2:C (ch)

    const int t = threadIdx.x;
    const int b = blockIdx.x;

    // ---- build the three 4x4 Givens products ----
    if (t < 3) {
        float M[16] = {1,0,0,0, 0,1,0,0, 0,0,1,0, 0,0,0,1};
        const int pi[6] = {0,0,0,1,1,2};
        const int pj[6] = {1,2,3,2,3,3};
#pragma unroll
        for (int g = 0; g < 6; ++g) {
            float th = thetas[t * 6 + g];
            float cc = cosf(th), sn = sinf(th);
            int i = pi[g], j = pj[g];
#pragma unroll
            for (int k = 0; k < 4; ++k) {
                float ai = M[i*4 + k], aj = M[j*4 + k];
                M[i*4 + k] =  cc * ai + sn * aj;   // M <- G * M
                M[j*4 + k] = -sn * ai + cc * aj;
            }
        }
#pragma unroll
        for (int k = 0; k < 16; ++k) sM[t][k] = M[k];
    }

    const float4* in4  = reinterpret_cast<const float4*>(in);
    float4*       out4 = reinterpret_cast<float4*>(out);

    if (b < 16) {
        // ================= type D: 64 rows {r<4,c<4} x 64 cols =============
        const int ccq = b & 3, chunk = b >> 2;   // c-quarter, rc-chunk
#pragma unroll
        for (int h = 0; h < 4; ++h) {
            int idx = t + 256*h;
            int l = idx >> 4, c4 = idx & 15;
            int rcl = c4 >> 2, w = c4 & 3;
            int grow = (l >> 4) * 64 + (l & 15);
            int gc4  = (chunk*4 + rcl)*16 + ccq*4 + w;
            float4 v = in4[grow*256 + gc4];
            *reinterpret_cast<float4*>(&s[l*RSD + rcl*20 + w*4]) = v;
        }
        __syncthreads();
        // row C (j) + row B (cc) fused in registers: thread owns (rr, col)
        {
            float C4[16], B4[16];
#pragma unroll
            for (int k = 0; k < 16; ++k) { C4[k] = sM[2][k]; B4[k] = sM[1][k]; }
            int rr = t >> 6, q = t & 63;
            int pc = q + 4*(q >> 4);
            float v[16];
#pragma unroll
            for (int k = 0; k < 16; ++k) v[k] = s[(rr*16 + k)*RSD + pc];
#pragma unroll
            for (int cc = 0; cc < 4; ++cc) mix4r(&v[cc*4], 1, C4);
#pragma unroll
            for (int j = 0; j < 4; ++j)    mix4r(&v[j], 4, B4);
#pragma unroll
            for (int k = 0; k < 16; ++k) s[(rr*16 + k)*RSD + pc] = v[k];
        }
        __syncthreads();
        // row A across rr (stride 16 rows)
        {
            float A4[16];
#pragma unroll
            for (int k = 0; k < 16; ++k) A4[k] = sM[0][k];
#pragma unroll
            for (int h = 0; h < 4; ++h) {
                int g = t + 256*h;
                int ccj = g >> 6, q = g & 63;
                int pc = q + 4*(q >> 4);
                mix4s(&s[ccj*RSD + pc], 16*RSD, A4);
            }
        }
        __syncthreads();
        // col C (jc, stride 1): 64 rows x 4 rcl x 4 ccl = 1024 groups
        {
            float C4[16];
#pragma unroll
            for (int k = 0; k < 16; ++k) C4[k] = sM[2][k];
#pragma unroll
            for (int h = 0; h < 4; ++h) {
                int g = t + 256*h;
                int l = g >> 4, rcl = (g >> 2) & 3, ccl = g & 3;
                mix4s(&s[l*RSD + rcl*20 + ccl*4], 1, C4);
            }
        }
        __syncthreads();
        // col B (c<4): only the ccq==0 quarter holds those columns
        if (ccq == 0) {
            float B4[16];
#pragma unroll
            for (int k = 0; k < 16; ++k) B4[k] = sM[1][k];
#pragma unroll
            for (int h = 0; h < 4; ++h) {
                int g = t + 256*h;
                int l = g >> 4, rcl = (g >> 2) & 3, j = g & 3;
                mix4s(&s[l*RSD + rcl*20 + j], 4, B4);
            }
            __syncthreads();
        }
        // col A (rc<4): only chunk 0
        if (chunk == 0) {
            float A4[16];
#pragma unroll
            for (int k = 0; k < 16; ++k) A4[k] = sM[0][k];
#pragma unroll
            for (int h = 0; h < 4; ++h) {
                int g = t + 256*h;
                int l = g >> 4, ccl = (g >> 2) & 3, j = g & 3;
                mix4s(&s[l*RSD + ccl*4 + j], 20, A4);
            }
            __syncthreads();
        }
        // store (mirror of load)
#pragma unroll
        for (int h = 0; h < 4; ++h) {
            int idx = t + 256*h;
            int l = idx >> 4, c4 = idx & 15;
            int rcl = c4 >> 2, w = c4 & 3;
            int grow = (l >> 4) * 64 + (l & 15);
            int gc4  = (chunk*4 + rcl)*16 + ccq*4 + w;
            out4[grow*256 + gc4] =
                *reinterpret_cast<float4*>(&s[l*RSD + rcl*20 + w*4]);
        }
    } else {
        // ============ 16-row classes x 256-col chunk =======================
        int typ, chunk, rb_r = 0, rb_c = 0, rb_c0 = 0;
        if (b < 64)       { typ = 0; int id = b - 16;  chunk = id & 3; rb_r = 4 + (id >> 2); }            // Bc: rows r*64 + l
        else if (b < 112) { typ = 1; int id = b - 64;  chunk = id & 3; rb_c = 4 + (id >> 2); }            // Cc: rows (l>>2)*64 + c*4 + (l&3)
        else              { typ = 2; int id = b - 112; chunk = id & 3; int g = id >> 2;
                            rb_r = 4 + g / 3; rb_c0 = 4 + (g % 3) * 4; }                                  // Am: rows r*64 + c0*4 + l
        // load 16 x 256
#pragma unroll
        for (int h = 0; h < 4; ++h) {
            int idx = t + 256*h;
            int l = idx >> 6, c4 = idx & 63;
            int grow = (typ == 0) ? rb_r*64 + l
                     : (typ == 1) ? (l >> 2)*64 + rb_c*4 + (l & 3)
                                  : rb_r*64 + rb_c0*4 + l;
            float4 v = in4[grow*256 + chunk*64 + c4];
            *reinterpret_cast<float4*>(&s[l*RS16 + (c4 >> 4)*68 + (c4 & 15)*4]) = v;
        }
        __syncthreads();
        // row mixing fully in registers: thread owns one column (16 values)
        {
            float C4[16], M2[16];
            const float* msrc = (typ == 0) ? sM[1] : sM[0];
#pragma unroll
            for (int k = 0; k < 16; ++k) { C4[k] = sM[2][k]; M2[k] = msrc[k]; }
            int pc = t + 4*(t >> 6);
            float v[16];
#pragma unroll
            for (int k = 0; k < 16; ++k) v[k] = s[k*RS16 + pc];
#pragma unroll
            for (int qd = 0; qd < 4; ++qd) mix4r(&v[qd*4], 1, C4);   // C on j
            if (typ != 2) {
#pragma unroll
                for (int j = 0; j < 4; ++j) mix4r(&v[j], 4, M2);     // B or A
            }
#pragma unroll
            for (int k = 0; k < 16; ++k) s[k*RS16 + pc] = v[k];
        }
        __syncthreads();
        // col C (jc): ALL 16 rows x 4 bl x 16 c = 1024 groups
        {
            float C4[16];
#pragma unroll
            for (int k = 0; k < 16; ++k) C4[k] = sM[2][k];
#pragma unroll
            for (int h = 0; h < 4; ++h) {
                int g = t + 256*h;
                int l = g >> 6, bl = (g >> 4) & 3, c = g & 15;
                mix4s(&s[l*RS16 + bl*68 + c*4], 1, C4);
            }
        }
        __syncthreads();
        // col B (c<4 within each 64-block): 16 x 4 x 4 = 256 groups
        {
            float B4[16];
#pragma unroll
            for (int k = 0; k < 16; ++k) B4[k] = sM[1][k];
            int l = t >> 4, bl = (t >> 2) & 3, j = t & 3;
            mix4s(&s[l*RS16 + bl*68 + j], 4, B4);
        }
        __syncthreads();
        // col A (rc<4): only chunk 0
        if (chunk == 0) {
            float A4[16];
#pragma unroll
            for (int k = 0; k < 16; ++k) A4[k] = sM[0][k];
#pragma unroll
            for (int h = 0; h < 4; ++h) {
                int g = t + 256*h;
                int l = g >> 6, cc = (g >> 2) & 15, j = g & 3;
                mix4s(&s[l*RS16 + cc*4 + j], 68, A4);
            }
            __syncthreads();
        }
        // store (mirror of load)
#pragma unroll
        for (int h = 0; h < 4; ++h) {
            int idx = t + 256*h;
            int l = idx >> 6, c4 = idx & 63;
            int grow = (typ == 0) ? rb_r*64 + l
                     : (typ == 1) ? (l >> 2)*64 + rb_c*4 + (l & 3)
                                  : rb_r*64 + rb_c0*4 + l;
            out4[grow*256 + chunk*64 + c4] =
                *reinterpret_cast<float4*>(&s[l*RS16 + (c4 >> 4)*68 + (c4 & 15)*4]);
        }
    }
}

extern "C" void kernel_launch(void* const* d_in, const int* in_sizes, int n_in,
                              void* d_out, int out_size)
{
    const float* state  = nullptr;
    const float* thetas = nullptr;
    for (int i = 0; i < n_in; ++i) {
        if (in_sizes[i] == 18 && !thetas)
            thetas = (const float*)d_in[i];
        else if (in_sizes[i] == 1024 * 1024 && !state)
            state = (const float*)d_in[i];
    }
    rbs_fused<<<256, 256>>>(state, (float*)d_out, thetas);
}

// round 13
// speedup vs baseline: 1.2537x; 1.1618x over previous
#include <cuda_runtime.h>

// FINAL — converged kernel.
// rho' = L rho L^T,  L = A (x) B (x) C  (flat index = r*64 + c*4 + j,
// r,c in [0,16), j in [0,4)).  A,B are identity outside indices 0..3, so the
// index space splits into independent coupling classes:
//   D : {r<4, c<4}                -> one class of 64 indices
//   Cc: {r<4, c fixed >=4}        -> 12 classes of 16
//   Bc: {r fixed >=4, c<4}        -> 12 classes of 16
//   Am: {r>=4, c>=4}              -> 144 classes of 4 (merged 4-at-a-time)
// out[I,J] = (L|I) rho[I,J] (L|J)^T per class pair, so ONE kernel: each block
// owns a row-class x column range of whole column classes, applies row mixing
// (in registers) and column mixing (in padded smem), reads/writes each element
// exactly once, fully coalesced. No scratch, no second pass, no transpose.
//
// Measured: 9.28 / 10.11 us wall (run-to-run noise ~ +/-0.8 us), rel_err
// 1.39e-7. Occupancy, sync-count, shuffle, and grid-shape restructures all
// measured neutral-to-worse; wall is pinned by graph-replay overhead plus a
// launch-dominated per-kernel cost, not by anything inside the kernel.

#define RS16 272   // 16-row tiles: 256 cols + 4 pad per 64-col block
#define RSD   80   // 64-row tiles:  64 cols + 4 pad per 16-col block

__device__ __forceinline__ void mix4s(float* p, const int st, const float* M)
{
    float v0 = p[0], v1 = p[st], v2 = p[2*st], v3 = p[3*st];
    p[0]    = M[0] *v0 + M[1] *v1 + M[2] *v2 + M[3] *v3;
    p[st]   = M[4] *v0 + M[5] *v1 + M[6] *v2 + M[7] *v3;
    p[2*st] = M[8] *v0 + M[9] *v1 + M[10]*v2 + M[11]*v3;
    p[3*st] = M[12]*v0 + M[13]*v1 + M[14]*v2 + M[15]*v3;
}

__device__ __forceinline__ void mix4r(float* v, const int st, const float* M)
{
    float v0 = v[0], v1 = v[st], v2 = v[2*st], v3 = v[3*st];
    v[0]    = M[0] *v0 + M[1] *v1 + M[2] *v2 + M[3] *v3;
    v[st]   = M[4] *v0 + M[5] *v1 + M[6] *v2 + M[7] *v3;
    v[2*st] = M[8] *v0 + M[9] *v1 + M[10]*v2 + M[11]*v3;
    v[3*st] = M[12]*v0 + M[13]*v1 + M[14]*v2 + M[15]*v3;
}

__global__ __launch_bounds__(256)
void rbs_fused(const float* __restrict__ in, float* __restrict__ out,
               const float* __restrict__ thetas)
{
    __shared__ float s[64 * RSD];   // 20480 B; 16*RS16 = 4352 floats also fits
    __shared__ float sM[3][16];     // 0:A (row gates), 1:B (col), 2:C (ch)

    const int t = threadIdx.x;
    const int b = blockIdx.x;

    // ---- build the three 4x4 Givens products ----
    if (t < 3) {
        float M[16] = {1,0,0,0, 0,1,0,0, 0,0,1,0, 0,0,0,1};
        const int pi[6] = {0,0,0,1,1,2};
        const int pj[6] = {1,2,3,2,3,3};
#pragma unroll
        for (int g = 0; g < 6; ++g) {
            float th = thetas[t * 6 + g];
            float cc = cosf(th), sn = sinf(th);
            int i = pi[g], j = pj[g];
#pragma unroll
            for (int k = 0; k < 4; ++k) {
                float ai = M[i*4 + k], aj = M[j*4 + k];
                M[i*4 + k] =  cc * ai + sn * aj;   // M <- G * M
                M[j*4 + k] = -sn * ai + cc * aj;
            }
        }
#pragma unroll
        for (int k = 0; k < 16; ++k) sM[t][k] = M[k];
    }

    const float4* in4  = reinterpret_cast<const float4*>(in);
    float4*       out4 = reinterpret_cast<float4*>(out);

    if (b < 16) {
        // ================= type D: 64 rows {r<4,c<4} x 64 cols =============
        const int ccq = b & 3, chunk = b >> 2;   // c-quarter, rc-chunk
#pragma unroll
        for (int h = 0; h < 4; ++h) {
            int idx = t + 256*h;
            int l = idx >> 4, c4 = idx & 15;
            int rcl = c4 >> 2, w = c4 & 3;
            int grow = (l >> 4) * 64 + (l & 15);
            int gc4  = (chunk*4 + rcl)*16 + ccq*4 + w;
            float4 v = in4[grow*256 + gc4];
            *reinterpret_cast<float4*>(&s[l*RSD + rcl*20 + w*4]) = v;
        }
        __syncthreads();
        // row C (j) + row B (cc) fused in registers: thread owns (rr, col)
        {
            float C4[16], B4[16];
#pragma unroll
            for (int k = 0; k < 16; ++k) { C4[k] = sM[2][k]; B4[k] = sM[1][k]; }
            int rr = t >> 6, q = t & 63;
            int pc = q + 4*(q >> 4);
            float v[16];
#pragma unroll
            for (int k = 0; k < 16; ++k) v[k] = s[(rr*16 + k)*RSD + pc];
#pragma unroll
            for (int cc = 0; cc < 4; ++cc) mix4r(&v[cc*4], 1, C4);
#pragma unroll
            for (int j = 0; j < 4; ++j)    mix4r(&v[j], 4, B4);
#pragma unroll
            for (int k = 0; k < 16; ++k) s[(rr*16 + k)*RSD + pc] = v[k];
        }
        __syncthreads();
        // row A across rr (stride 16 rows)
        {
            float A4[16];
#pragma unroll
            for (int k = 0; k < 16; ++k) A4[k] = sM[0][k];
#pragma unroll
            for (int h = 0; h < 4; ++h) {
                int g = t + 256*h;
                int ccj = g >> 6, q = g & 63;
                int pc = q + 4*(q >> 4);
                mix4s(&s[ccj*RSD + pc], 16*RSD, A4);
            }
        }
        __syncthreads();
        // col C (jc, stride 1): 64 rows x 4 rcl x 4 ccl = 1024 groups
        {
            float C4[16];
#pragma unroll
            for (int k = 0; k < 16; ++k) C4[k] = sM[2][k];
#pragma unroll
            for (int h = 0; h < 4; ++h) {
                int g = t + 256*h;
                int l = g >> 4, rcl = (g >> 2) & 3, ccl = g & 3;
                mix4s(&s[l*RSD + rcl*20 + ccl*4], 1, C4);
            }
        }
        __syncthreads();
        // col B (c<4): only the ccq==0 quarter holds those columns
        if (ccq == 0) {
            float B4[16];
#pragma unroll
            for (int k = 0; k < 16; ++k) B4[k] = sM[1][k];
#pragma unroll
            for (int h = 0; h < 4; ++h) {
                int g = t + 256*h;
                int l = g >> 4, rcl = (g >> 2) & 3, j = g & 3;
                mix4s(&s[l*RSD + rcl*20 + j], 4, B4);
            }
            __syncthreads();
        }
        // col A (rc<4): only chunk 0
        if (chunk == 0) {
            float A4[16];
#pragma unroll
            for (int k = 0; k < 16; ++k) A4[k] = sM[0][k];
#pragma unroll
            for (int h = 0; h < 4; ++h) {
                int g = t + 256*h;
                int l = g >> 4, ccl = (g >> 2) & 3, j = g & 3;
                mix4s(&s[l*RSD + ccl*4 + j], 20, A4);
            }
            __syncthreads();
        }
        // store (mirror of load)
#pragma unroll
        for (int h = 0; h < 4; ++h) {
            int idx = t + 256*h;
            int l = idx >> 4, c4 = idx & 15;
            int rcl = c4 >> 2, w = c4 & 3;
            int grow = (l >> 4) * 64 + (l & 15);
            int gc4  = (chunk*4 + rcl)*16 + ccq*4 + w;
            out4[grow*256 + gc4] =
                *reinterpret_cast<float4*>(&s[l*RSD + rcl*20 + w*4]);
        }
    } else {
        // ============ 16-row classes x 256-col chunk =======================
        int typ, chunk, rb_r = 0, rb_c = 0, rb_c0 = 0;
        if (b < 64)       { typ = 0; int id = b - 16;  chunk = id & 3; rb_r = 4 + (id >> 2); }            // Bc: rows r*64 + l
        else if (b < 112) { typ = 1; int id = b - 64;  chunk = id & 3; rb_c = 4 + (id >> 2); }            // Cc: rows (l>>2)*64 + c*4 + (l&3)
        else              { typ = 2; int id = b - 112; chunk = id & 3; int g = id >> 2;
                            rb_r = 4 + g / 3; rb_c0 = 4 + (g % 3) * 4; }                                  // Am: rows r*64 + c0*4 + l
        // load 16 x 256
#pragma unroll
        for (int h = 0; h < 4; ++h) {
            int idx = t + 256*h;
            int l = idx >> 6, c4 = idx & 63;
            int grow = (typ == 0) ? rb_r*64 + l
                     : (typ == 1) ? (l >> 2)*64 + rb_c*4 + (l & 3)
                                  : rb_r*64 + rb_c0*4 + l;
            float4 v = in4[grow*256 + chunk*64 + c4];
            *reinterpret_cast<float4*>(&s[l*RS16 + (c4 >> 4)*68 + (c4 & 15)*4]) = v;
        }
        __syncthreads();
        // row mixing fully in registers: thread owns one column (16 values)
        {
            float C4[16], M2[16];
            const float* msrc = (typ == 0) ? sM[1] : sM[0];
#pragma unroll
            for (int k = 0; k < 16; ++k) { C4[k] = sM[2][k]; M2[k] = msrc[k]; }
            int pc = t + 4*(t >> 6);
            float v[16];
#pragma unroll
            for (int k = 0; k < 16; ++k) v[k] = s[k*RS16 + pc];
#pragma unroll
            for (int qd = 0; qd < 4; ++qd) mix4r(&v[qd*4], 1, C4);   // C on j
            if (typ != 2) {
#pragma unroll
                for (int j = 0; j < 4; ++j) mix4r(&v[j], 4, M2);     // B or A
            }
#pragma unroll
            for (int k = 0; k < 16; ++k) s[k*RS16 + pc] = v[k];
        }
        __syncthreads();
        // col C (jc): ALL 16 rows x 4 bl x 16 c = 1024 groups
        {
            float C4[16];
#pragma unroll
            for (int k = 0; k < 16; ++k) C4[k] = sM[2][k];
#pragma unroll
            for (int h = 0; h < 4; ++h) {
                int g = t + 256*h;
                int l = g >> 6, bl = (g >> 4) & 3, c = g & 15;
                mix4s(&s[l*RS16 + bl*68 + c*4], 1, C4);
            }
        }
        __syncthreads();
        // col B (c<4 within each 64-block): 16 x 4 x 4 = 256 groups
        {
            float B4[16];
#pragma unroll
            for (int k = 0; k < 16; ++k) B4[k] = sM[1][k];
            int l = t >> 4, bl = (t >> 2) & 3, j = t & 3;
            mix4s(&s[l*RS16 + bl*68 + j], 4, B4);
        }
        __syncthreads();
        // col A (rc<4): only chunk 0
        if (chunk == 0) {
            float A4[16];
#pragma unroll
            for (int k = 0; k < 16; ++k) A4[k] = sM[0][k];
#pragma unroll
            for (int h = 0; h < 4; ++h) {
                int g = t + 256*h;
                int l = g >> 6, cc = (g >> 2) & 15, j = g & 3;
                mix4s(&s[l*RS16 + cc*4 + j], 68, A4);
            }
            __syncthreads();
        }
        // store (mirror of load)
#pragma unroll
        for (int h = 0; h < 4; ++h) {
            int idx = t + 256*h;
            int l = idx >> 6, c4 = idx & 63;
            int grow = (typ == 0) ? rb_r*64 + l
                     : (typ == 1) ? (l >> 2)*64 + rb_c*4 + (l & 3)
                                  : rb_r*64 + rb_c0*4 + l;
            out4[grow*256 + chunk*64 + c4] =
                *reinterpret_cast<float4*>(&s[l*RS16 + (c4 >> 4)*68 + (c4 & 15)*4]);
        }
    }
}

extern "C" void kernel_launch(void* const* d_in, const int* in_sizes, int n_in,
                              void* d_out, int out_size)
{
    const float* state  = nullptr;
    const float* thetas = nullptr;
    for (int i = 0; i < n_in; ++i) {
        if (in_sizes[i] == 18 && !thetas)
            thetas = (const float*)d_in[i];
        else if (in_sizes[i] == 1024 * 1024 && !state)
            state = (const float*)d_in[i];
    }
    rbs_fused<<<256, 256>>>(state, (float*)d_out, thetas);
}